// round 1
// baseline (speedup 1.0000x reference)
#include <cuda_runtime.h>

#define S_TILE   16
#define KF       32
#define ROWS     48            // S_TILE + KF
#define DCONST   1024
#define D4       256           // D / 4
#define PITCH4   257           // float4 pitch per row (1028 floats) -> odd => conflict-free strided rows
#define COLS     48            // score columns (j = 0..47), query i uses j in [i+1, i+32]
#define NEG_BIG  -1.0e9f

// shared memory layout (in floats):
//   tile : ROWS * PITCH4 * 4   = 49344 floats (197376 B)
//   red  : 8 * S_TILE * COLS   =  6144 floats (24576 B)   -- per-warp partial scores
//   Wbuf : S_TILE * COLS       =   768 floats (3072 B)    -- scores then softmax weights
#define TILE_F4      (ROWS * PITCH4)         // 12336 float4
#define RED_OFF      (TILE_F4 * 4)           // 49344
#define RED_SIZE     (8 * S_TILE * COLS)     // 6144
#define W_OFF        (RED_OFF + RED_SIZE)    // 55488
#define SMEM_FLOATS  (W_OFF + S_TILE * COLS) // 56256 floats
#define SMEM_BYTES   (SMEM_FLOATS * 4)       // 225024 B

__global__ __launch_bounds__(256, 1)
void future_encoder_kernel(const float* __restrict__ in,
                           float* __restrict__ out,
                           int S)
{
    extern __shared__ float smem[];
    float4* tile4 = reinterpret_cast<float4*>(smem);
    float*  red   = smem + RED_OFF;
    float*  Wbuf  = smem + W_OFF;

    const int tid = threadIdx.x;
    const int s0  = blockIdx.x * S_TILE;
    const int bb  = blockIdx.y;

    const float4* in4 = reinterpret_cast<const float4*>(in) + (size_t)bb * S * D4;

    // ---- load 48 rows x 1024 floats into smem (rows clamped; clamped rows get masked later) ----
    #pragma unroll 4
    for (int r = 0; r < ROWS; ++r) {
        int gr = s0 + r;
        if (gr > S - 1) gr = S - 1;
        tile4[r * PITCH4 + tid] = in4[(size_t)gr * D4 + tid];
    }
    __syncthreads();

    // ---- Phase A: partial scores C[i][j] = dot(R[i], R[j]) over this warp's 128 dims ----
    {
        const int g    = tid >> 5;        // warp id = dim group (g*128 .. g*128+127)
        const int lane = tid & 31;
        const int a    = lane >> 3;       // i-block: rows a*4 .. a*4+3
        const int b    = lane & 7;        // j-base : cols b, b+8, ..., b+40

        float acc[4][6];
        #pragma unroll
        for (int ii = 0; ii < 4; ++ii)
            #pragma unroll
            for (int jj = 0; jj < 6; ++jj)
                acc[ii][jj] = 0.0f;

        const int base = g * 32;          // float4 column start for this warp

        #pragma unroll 4
        for (int step = 0; step < 32; ++step) {
            const int col = base + step;
            float4 q[4], f[6];
            #pragma unroll
            for (int ii = 0; ii < 4; ++ii)
                q[ii] = tile4[(a * 4 + ii) * PITCH4 + col];
            #pragma unroll
            for (int jj = 0; jj < 6; ++jj)
                f[jj] = tile4[(b + 8 * jj) * PITCH4 + col];
            #pragma unroll
            for (int ii = 0; ii < 4; ++ii)
                #pragma unroll
                for (int jj = 0; jj < 6; ++jj) {
                    float t = acc[ii][jj];
                    t = fmaf(q[ii].x, f[jj].x, t);
                    t = fmaf(q[ii].y, f[jj].y, t);
                    t = fmaf(q[ii].z, f[jj].z, t);
                    t = fmaf(q[ii].w, f[jj].w, t);
                    acc[ii][jj] = t;
                }
        }

        float* myred = red + g * (S_TILE * COLS);
        #pragma unroll
        for (int ii = 0; ii < 4; ++ii)
            #pragma unroll
            for (int jj = 0; jj < 6; ++jj)
                myred[(a * 4 + ii) * COLS + (b + 8 * jj)] = acc[ii][jj];
    }
    __syncthreads();

    // ---- reduce partials across the 8 dim-groups + apply band/tail mask ----
    #pragma unroll
    for (int e = tid; e < S_TILE * COLS; e += 256) {
        float s = 0.0f;
        #pragma unroll
        for (int g = 0; g < 8; ++g)
            s += red[g * (S_TILE * COLS) + e];
        const int i = e / COLS;
        const int j = e % COLS;
        const int k = j - i - 1;
        const bool valid = (k >= 0) && (k < KF) && (s0 + j < S);
        Wbuf[e] = valid ? s : NEG_BIG;
    }
    __syncthreads();

    // ---- softmax per query row (8 warps x 2 rows); explicitly zero invalid weights ----
    {
        const int w    = tid >> 5;
        const int lane = tid & 31;
        #pragma unroll
        for (int rr = 0; rr < 2; ++rr) {
            const int row = w * 2 + rr;
            const float v1 = Wbuf[row * COLS + lane];
            const float v2 = (lane < 16) ? Wbuf[row * COLS + 32 + lane] : NEG_BIG;
            float m = fmaxf(v1, v2);
            #pragma unroll
            for (int o = 16; o > 0; o >>= 1)
                m = fmaxf(m, __shfl_xor_sync(0xFFFFFFFFu, m, o));
            const float e1 = __expf(v1 - m);
            const float e2 = (lane < 16) ? __expf(v2 - m) : 0.0f;
            float sum = e1 + e2;
            #pragma unroll
            for (int o = 16; o > 0; o >>= 1)
                sum += __shfl_xor_sync(0xFFFFFFFFu, sum, o);
            const float inv = 1.0f / sum;

            {
                const int j1 = lane;
                const int k1 = j1 - row - 1;
                const bool val1 = (k1 >= 0) && (k1 < KF) && (s0 + j1 < S);
                Wbuf[row * COLS + j1] = val1 ? e1 * inv : 0.0f;
            }
            if (lane < 16) {
                const int j2 = 32 + lane;
                const int k2 = j2 - row - 1;
                const bool val2 = (k2 >= 0) && (k2 < KF) && (s0 + j2 < S);
                Wbuf[row * COLS + j2] = val2 ? e2 * inv : 0.0f;
            }
        }
    }
    __syncthreads();

    // ---- Phase B: out[i][:] = sum_j W[i][j] * R[j][:]  (zero weights handle all masking) ----
    {
        const int a = tid >> 6;   // i-block: rows a*4 .. a*4+3
        const int b = tid & 63;   // float4 columns: b, b+64, b+128, b+192

        float4 acc[4][4];
        #pragma unroll
        for (int ii = 0; ii < 4; ++ii)
            #pragma unroll
            for (int c = 0; c < 4; ++c)
                acc[ii][c] = make_float4(0.f, 0.f, 0.f, 0.f);

        #pragma unroll 4
        for (int j = 0; j < COLS; ++j) {
            float wv[4];
            #pragma unroll
            for (int ii = 0; ii < 4; ++ii)
                wv[ii] = Wbuf[(a * 4 + ii) * COLS + j];
            float4 f[4];
            #pragma unroll
            for (int c = 0; c < 4; ++c)
                f[c] = tile4[j * PITCH4 + b + 64 * c];
            #pragma unroll
            for (int ii = 0; ii < 4; ++ii)
                #pragma unroll
                for (int c = 0; c < 4; ++c) {
                    acc[ii][c].x = fmaf(wv[ii], f[c].x, acc[ii][c].x);
                    acc[ii][c].y = fmaf(wv[ii], f[c].y, acc[ii][c].y);
                    acc[ii][c].z = fmaf(wv[ii], f[c].z, acc[ii][c].z);
                    acc[ii][c].w = fmaf(wv[ii], f[c].w, acc[ii][c].w);
                }
        }

        float4* out4 = reinterpret_cast<float4*>(out) + (size_t)bb * S * D4;
        #pragma unroll
        for (int ii = 0; ii < 4; ++ii) {
            const int s = s0 + a * 4 + ii;
            if (s < S) {
                #pragma unroll
                for (int c = 0; c < 4; ++c)
                    out4[(size_t)s * D4 + b + 64 * c] = acc[ii][c];
            }
        }
    }
}

extern "C" void kernel_launch(void* const* d_in, const int* in_sizes, int n_in,
                              void* d_out, int out_size)
{
    (void)n_in; (void)out_size;
    const float* in = (const float*)d_in[0];
    float* out = (float*)d_out;

    const int S = 2048;
    const int Dm = DCONST;
    const int B = in_sizes[0] / (S * Dm);

    cudaFuncSetAttribute(future_encoder_kernel,
                         cudaFuncAttributeMaxDynamicSharedMemorySize,
                         SMEM_BYTES);

    dim3 grid((S + S_TILE - 1) / S_TILE, B);
    future_encoder_kernel<<<grid, 256, SMEM_BYTES>>>(in, out, S);
}

// round 2
// speedup vs baseline: 1.0947x; 1.0947x over previous
#include <cuda_runtime.h>

#define S_TILE   16
#define KF       32
#define ROWS     48            // S_TILE + KF
#define DCONST   1024
#define D4       256           // D / 4
#define PITCH4   257           // float4 pitch -> rows shift 4 floats/row across banks
#define COLS     48
#define NEG_BIG  -1.0e9f

// smem layout (floats):
//   tile : ROWS * PITCH4 * 4      = 49344 floats (197376 B)
//   red  : 8 * S_TILE * COLS      =  6144 floats (24576 B)
//   Wdup : S_TILE * COLS float2   =  1536 floats (6144 B)   -- duplicated weights for f32x2
#define TILE_F4      (ROWS * PITCH4)          // 12336 float4
#define RED_OFF      (TILE_F4 * 4)            // 49344
#define RED_SIZE     (8 * S_TILE * COLS)      // 6144
#define W_OFF        (RED_OFF + RED_SIZE)     // 55488 (byte 221952, 8B aligned)
#define SMEM_FLOATS  (W_OFF + S_TILE * COLS * 2)
#define SMEM_BYTES   (SMEM_FLOATS * 4)        // 228096 B

typedef unsigned long long u64;

__device__ __forceinline__ void fma2(u64& d, u64 a, u64 b) {
    asm("fma.rn.f32x2 %0, %1, %2, %0;" : "+l"(d) : "l"(a), "l"(b));
}
__device__ __forceinline__ float sum2(u64 a) {
    float2 v = *reinterpret_cast<float2*>(&a);
    return v.x + v.y;
}

__global__ __launch_bounds__(512, 1)
void future_encoder_kernel(const float* __restrict__ in,
                           float* __restrict__ out,
                           int S)
{
    extern __shared__ float smem[];
    ulonglong2* tileU = reinterpret_cast<ulonglong2*>(smem);
    float4*     tile4 = reinterpret_cast<float4*>(smem);
    float*      red   = smem + RED_OFF;
    u64*        Wd    = reinterpret_cast<u64*>(smem + W_OFF);
    float2*     Wd2   = reinterpret_cast<float2*>(smem + W_OFF);

    const int tid = threadIdx.x;
    const int s0  = blockIdx.x * S_TILE;
    const int bb  = blockIdx.y;

    const float4* in4 = reinterpret_cast<const float4*>(in) + (size_t)bb * S * D4;

    // ---- load 48 rows x 1024 floats (2 rows per iteration across 512 threads) ----
    {
        const int half = tid >> 8;       // 0/1
        const int col  = tid & 255;
        #pragma unroll 4
        for (int it = 0; it < 24; ++it) {
            const int r = it * 2 + half;
            int gr = s0 + r;
            if (gr > S - 1) gr = S - 1;
            tile4[r * PITCH4 + col] = in4[(size_t)gr * D4 + col];
        }
    }
    __syncthreads();

    // ---- Phase A: partial scores over 128 dims per dim-group; 2 warps split j ----
    {
        const int w    = tid >> 5;
        const int lane = tid & 31;
        const int g    = w >> 1;          // dim group 0..7
        const int j0   = (w & 1) * 24;    // j half: cols j0..j0+23
        const int a    = lane >> 3;       // query rows a, a+4, a+8, a+12 (strided: conflict-free)
        const int b    = lane & 7;        // cols j0+b, j0+b+8, j0+b+16

        u64 acc[4][3];
        #pragma unroll
        for (int ii = 0; ii < 4; ++ii)
            #pragma unroll
            for (int jj = 0; jj < 3; ++jj)
                acc[ii][jj] = 0ull;

        const int base = g * 32;          // float4 column start

        #pragma unroll 4
        for (int step = 0; step < 32; ++step) {
            const int col = base + step;
            ulonglong2 q[4], f[3];
            #pragma unroll
            for (int ii = 0; ii < 4; ++ii)
                q[ii] = tileU[(a + 4 * ii) * PITCH4 + col];
            #pragma unroll
            for (int jj = 0; jj < 3; ++jj)
                f[jj] = tileU[(j0 + b + 8 * jj) * PITCH4 + col];
            #pragma unroll
            for (int ii = 0; ii < 4; ++ii)
                #pragma unroll
                for (int jj = 0; jj < 3; ++jj) {
                    fma2(acc[ii][jj], q[ii].x, f[jj].x);
                    fma2(acc[ii][jj], q[ii].y, f[jj].y);
                }
        }

        float* myred = red + g * (S_TILE * COLS);
        #pragma unroll
        for (int ii = 0; ii < 4; ++ii)
            #pragma unroll
            for (int jj = 0; jj < 3; ++jj)
                myred[(a + 4 * ii) * COLS + (j0 + b + 8 * jj)] = sum2(acc[ii][jj]);
    }
    __syncthreads();

    // ---- reduce over 8 dim-groups + mask + softmax (one warp per query row) ----
    {
        const int w    = tid >> 5;        // row 0..15
        const int lane = tid & 31;
        const int row  = w;

        float s1 = 0.0f, s2 = 0.0f;
        #pragma unroll
        for (int g = 0; g < 8; ++g)
            s1 += red[g * (S_TILE * COLS) + row * COLS + lane];
        if (lane < 16) {
            #pragma unroll
            for (int g = 0; g < 8; ++g)
                s2 += red[g * (S_TILE * COLS) + row * COLS + 32 + lane];
        }

        const int j1 = lane;
        const int k1 = j1 - row - 1;
        const bool val1 = (k1 >= 0) && (k1 < KF) && (s0 + j1 < S);
        const float v1 = val1 ? s1 : NEG_BIG;

        const int j2 = 32 + lane;
        const int k2 = j2 - row - 1;
        const bool val2 = (lane < 16) && (k2 >= 0) && (k2 < KF) && (s0 + j2 < S);
        const float v2 = val2 ? s2 : NEG_BIG;

        float m = fmaxf(v1, v2);
        #pragma unroll
        for (int o = 16; o > 0; o >>= 1)
            m = fmaxf(m, __shfl_xor_sync(0xFFFFFFFFu, m, o));

        const float e1 = __expf(v1 - m);
        const float e2 = (lane < 16) ? __expf(v2 - m) : 0.0f;
        float sum = e1 + e2;
        #pragma unroll
        for (int o = 16; o > 0; o >>= 1)
            sum += __shfl_xor_sync(0xFFFFFFFFu, sum, o);
        const float inv = 1.0f / sum;

        const float w1 = val1 ? e1 * inv : 0.0f;
        Wd2[row * COLS + j1] = make_float2(w1, w1);
        if (lane < 16) {
            const float w2 = val2 ? e2 * inv : 0.0f;
            Wd2[row * COLS + j2] = make_float2(w2, w2);
        }
    }
    __syncthreads();

    // ---- Phase B: out[i][:] = sum_j W[i][j] * R[j][:]  (8 rows x 1 float4-col per thread) ----
    {
        const int a = tid >> 8;    // 0/1 -> rows a*8 .. a*8+7
        const int b = tid & 255;   // float4 column

        u64 acc[8][2];
        #pragma unroll
        for (int ii = 0; ii < 8; ++ii) {
            acc[ii][0] = 0ull;
            acc[ii][1] = 0ull;
        }

        #pragma unroll 4
        for (int j = 0; j < COLS; ++j) {
            const ulonglong2 f = tileU[j * PITCH4 + b];
            #pragma unroll
            for (int ii = 0; ii < 8; ++ii) {
                const u64 wp = Wd[(a * 8 + ii) * COLS + j];   // broadcast LDS.64 (dup weight)
                fma2(acc[ii][0], wp, f.x);
                fma2(acc[ii][1], wp, f.y);
            }
        }

        float4* out4 = reinterpret_cast<float4*>(out) + (size_t)bb * S * D4;
        #pragma unroll
        for (int ii = 0; ii < 8; ++ii) {
            const int s = s0 + a * 8 + ii;
            if (s < S) {
                const float2 lo = *reinterpret_cast<float2*>(&acc[ii][0]);
                const float2 hi = *reinterpret_cast<float2*>(&acc[ii][1]);
                out4[(size_t)s * D4 + b] = make_float4(lo.x, lo.y, hi.x, hi.y);
            }
        }
    }
}

extern "C" void kernel_launch(void* const* d_in, const int* in_sizes, int n_in,
                              void* d_out, int out_size)
{
    (void)n_in; (void)out_size;
    const float* in = (const float*)d_in[0];
    float* out = (float*)d_out;

    const int S = 2048;
    const int B = in_sizes[0] / (S * DCONST);

    cudaFuncSetAttribute(future_encoder_kernel,
                         cudaFuncAttributeMaxDynamicSharedMemorySize,
                         SMEM_BYTES);

    dim3 grid((S + S_TILE - 1) / S_TILE, B);
    future_encoder_kernel<<<grid, 512, SMEM_BYTES>>>(in, out, S);
}

// round 3
// speedup vs baseline: 1.1239x; 1.0267x over previous
#include <cuda_runtime.h>

#define S_TILE   16
#define KF       32
#define ROWS     48            // S_TILE + KF (ring buffer size)
#define CHAIN    4             // s-tiles per CTA
#define DCONST   1024
#define D4       256           // D / 4
#define PITCH4   257           // float4 pitch per row
#define COLS     48
#define NEG_BIG  -1.0e9f

// smem (floats):
//   tile : ROWS * PITCH4 * 4   = 49344 (197376 B)
//   red  : 8 * S_TILE * COLS   =  6144 (24576 B)
//   Wdup : S_TILE * COLS u64   =  1536 (6144 B)
#define TILE_F4      (ROWS * PITCH4)
#define RED_OFF      (TILE_F4 * 4)            // 49344
#define RED_SIZE     (8 * S_TILE * COLS)
#define W_OFF        (RED_OFF + RED_SIZE)     // 55488 (byte 221952: 16B aligned)
#define SMEM_FLOATS  (W_OFF + S_TILE * COLS * 2)
#define SMEM_BYTES   (SMEM_FLOATS * 4)        // 228096 B

typedef unsigned long long u64;

__device__ __forceinline__ void fma2(u64& d, u64 a, u64 b) {
    asm("fma.rn.f32x2 %0, %1, %2, %0;" : "+l"(d) : "l"(a), "l"(b));
}
__device__ __forceinline__ float sum2(u64 a) {
    float2 v = *reinterpret_cast<float2*>(&a);
    return v.x + v.y;
}

__global__ __launch_bounds__(512, 1)
void future_encoder_kernel(const float* __restrict__ in,
                           float* __restrict__ out,
                           int S)
{
    extern __shared__ float smem[];
    ulonglong2* tileU = reinterpret_cast<ulonglong2*>(smem);
    float4*     tile4 = reinterpret_cast<float4*>(smem);
    float*      red   = smem + RED_OFF;
    u64*        Wd    = reinterpret_cast<u64*>(smem + W_OFF);
    float2*     Wd2   = reinterpret_cast<float2*>(smem + W_OFF);

    const int tid   = threadIdx.x;
    const int chain = blockIdx.x;
    const int bb    = blockIdx.y;
    const int t0    = chain * CHAIN;

    const float4* in4  = reinterpret_cast<const float4*>(in)  + (size_t)bb * S * D4;
    float4*       out4 = reinterpret_cast<float4*>(out)       + (size_t)bb * S * D4;

    // ---- initial load: 48 rows into slots 0..47 ----
    {
        const int half = tid >> 8;
        const int col  = tid & 255;
        #pragma unroll 4
        for (int it = 0; it < 24; ++it) {
            const int r = it * 2 + half;
            int gr = t0 * S_TILE + r;
            if (gr > S - 1) gr = S - 1;
            tile4[r * PITCH4 + col] = in4[(size_t)gr * D4 + col];
        }
    }

    int rot = 0;

    for (int tt = 0; tt < CHAIN; ++tt) {
        const int s0 = (t0 + tt) * S_TILE;
        __syncthreads();   // loads/refresh visible

        // ---- Phase A: partial scores; warp = (dim-group g, j-half) ----
        {
            const int w    = tid >> 5;
            const int lane = tid & 31;
            const int g    = w >> 1;
            const int j0   = (w & 1) * 24;
            const int a    = lane >> 3;      // q rows a, a+4, a+8, a+12 (logical)
            const int b    = lane & 7;       // f cols j0+b, +8, +16 (logical)

            int qs[4], fs[3];
            #pragma unroll
            for (int ii = 0; ii < 4; ++ii) {
                int r = a + 4 * ii + rot; if (r >= ROWS) r -= ROWS;
                qs[ii] = r * PITCH4;
            }
            #pragma unroll
            for (int jj = 0; jj < 3; ++jj) {
                int r = j0 + b + 8 * jj + rot; if (r >= ROWS) r -= ROWS;
                fs[jj] = r * PITCH4;
            }

            u64 acc[4][3];
            #pragma unroll
            for (int ii = 0; ii < 4; ++ii)
                #pragma unroll
                for (int jj = 0; jj < 3; ++jj)
                    acc[ii][jj] = 0ull;

            const int base = g * 32;
            #pragma unroll 4
            for (int step = 0; step < 32; ++step) {
                const int col = base + step;
                ulonglong2 q[4], f[3];
                #pragma unroll
                for (int ii = 0; ii < 4; ++ii)
                    q[ii] = tileU[qs[ii] + col];
                #pragma unroll
                for (int jj = 0; jj < 3; ++jj)
                    f[jj] = tileU[fs[jj] + col];
                #pragma unroll
                for (int ii = 0; ii < 4; ++ii)
                    #pragma unroll
                    for (int jj = 0; jj < 3; ++jj) {
                        fma2(acc[ii][jj], q[ii].x, f[jj].x);
                        fma2(acc[ii][jj], q[ii].y, f[jj].y);
                    }
            }

            float* myred = red + g * (S_TILE * COLS);
            #pragma unroll
            for (int ii = 0; ii < 4; ++ii)
                #pragma unroll
                for (int jj = 0; jj < 3; ++jj)
                    myred[(a + 4 * ii) * COLS + (j0 + b + 8 * jj)] = sum2(acc[ii][jj]);
        }
        __syncthreads();

        // ---- reduce over dim-groups + mask + softmax (warp w = query row w) ----
        {
            const int row  = tid >> 5;
            const int lane = tid & 31;

            float s1 = 0.0f, s2 = 0.0f;
            #pragma unroll
            for (int g = 0; g < 8; ++g)
                s1 += red[g * (S_TILE * COLS) + row * COLS + lane];
            if (lane < 16) {
                #pragma unroll
                for (int g = 0; g < 8; ++g)
                    s2 += red[g * (S_TILE * COLS) + row * COLS + 32 + lane];
            }

            const int j1 = lane;
            const int k1 = j1 - row - 1;
            const bool val1 = (k1 >= 0) && (k1 < KF) && (s0 + j1 < S);
            const float v1 = val1 ? s1 : NEG_BIG;

            const int j2 = 32 + lane;
            const int k2 = j2 - row - 1;
            const bool val2 = (lane < 16) && (k2 >= 0) && (k2 < KF) && (s0 + j2 < S);
            const float v2 = val2 ? s2 : NEG_BIG;

            float m = fmaxf(v1, v2);
            #pragma unroll
            for (int o = 16; o > 0; o >>= 1)
                m = fmaxf(m, __shfl_xor_sync(0xFFFFFFFFu, m, o));

            const float e1 = __expf(v1 - m);
            const float e2 = (lane < 16) ? __expf(v2 - m) : 0.0f;
            float sum = e1 + e2;
            #pragma unroll
            for (int o = 16; o > 0; o >>= 1)
                sum += __shfl_xor_sync(0xFFFFFFFFu, sum, o);
            const float inv = 1.0f / sum;

            const float w1 = val1 ? e1 * inv : 0.0f;
            Wd2[row * COLS + j1] = make_float2(w1, w1);
            if (lane < 16) {
                const float w2 = val2 ? e2 * inv : 0.0f;
                Wd2[row * COLS + j2] = make_float2(w2, w2);
            }
        }
        __syncthreads();

        // ---- Phase B: out[i][:] = sum_j W[i][j] * R[j][:] ----
        {
            const int a = tid >> 8;     // rows a*8 .. a*8+7
            const int b = tid & 255;    // float4 column

            u64 acc[8][2];
            #pragma unroll
            for (int ii = 0; ii < 8; ++ii) { acc[ii][0] = 0ull; acc[ii][1] = 0ull; }

            #pragma unroll 2
            for (int jp = 0; jp < 24; ++jp) {
                const int jl = jp * 2;
                int sl1 = jl + rot;     if (sl1 >= ROWS) sl1 -= ROWS;
                int sl2 = jl + 1 + rot; if (sl2 >= ROWS) sl2 -= ROWS;
                const ulonglong2 f1 = tileU[sl1 * PITCH4 + b];
                const ulonglong2 f2 = tileU[sl2 * PITCH4 + b];
                #pragma unroll
                for (int ii = 0; ii < 8; ++ii) {
                    // one LDS.128 broadcast: duplicated weights for j, j+1
                    const ulonglong2 wp =
                        *reinterpret_cast<const ulonglong2*>(&Wd[(a * 8 + ii) * COLS + jl]);
                    fma2(acc[ii][0], wp.x, f1.x);
                    fma2(acc[ii][1], wp.x, f1.y);
                    fma2(acc[ii][0], wp.y, f2.x);
                    fma2(acc[ii][1], wp.y, f2.y);
                }
            }

            #pragma unroll
            for (int ii = 0; ii < 8; ++ii) {
                const int s = s0 + a * 8 + ii;
                if (s < S) {
                    const float2 lo = *reinterpret_cast<float2*>(&acc[ii][0]);
                    const float2 hi = *reinterpret_cast<float2*>(&acc[ii][1]);
                    out4[(size_t)s * D4 + b] = make_float4(lo.x, lo.y, hi.x, hi.y);
                }
            }
        }

        // ---- ring refresh: 16 new rows for next tile ----
        if (tt + 1 < CHAIN) {
            __syncthreads();   // phase B reads done before overwrite
            const int half = tid >> 8;
            const int col  = tid & 255;
            #pragma unroll
            for (int it = 0; it < 8; ++it) {
                const int k = it * 2 + half;          // 0..15
                int slot = rot + k; if (slot >= ROWS) slot -= ROWS;
                int gr = s0 + ROWS + k;               // global row s0+48+k
                if (gr > S - 1) gr = S - 1;
                tile4[slot * PITCH4 + col] = in4[(size_t)gr * D4 + col];
            }
            rot += S_TILE; if (rot >= ROWS) rot -= ROWS;
        }
    }
}

extern "C" void kernel_launch(void* const* d_in, const int* in_sizes, int n_in,
                              void* d_out, int out_size)
{
    (void)n_in; (void)out_size;
    const float* in = (const float*)d_in[0];
    float* out = (float*)d_out;

    const int S = 2048;
    const int B = in_sizes[0] / (S * DCONST);
    const int chains = S / (S_TILE * CHAIN);   // 32

    cudaFuncSetAttribute(future_encoder_kernel,
                         cudaFuncAttributeMaxDynamicSharedMemorySize,
                         SMEM_BYTES);

    dim3 grid(chains, B);
    future_encoder_kernel<<<grid, 512, SMEM_BYTES>>>(in, out, S);
}